// round 1
// baseline (speedup 1.0000x reference)
#include <cuda_runtime.h>

#define C_DIM 256
#define L_DIM 1024
#define B_DIM 16
#define NH 8
#define DH 32
#define SCALE 0.17677669529663687f  // 32^-0.5

// Scratch (static device globals -- no allocation at runtime)
__device__ float g_q[B_DIM * C_DIM * L_DIM];
__device__ float g_k[B_DIM * C_DIM * L_DIM];
__device__ float g_v[B_DIM * C_DIM * L_DIM];
__device__ float g_att[B_DIM * C_DIM * L_DIM];

// ---------------------------------------------------------------------------
// Tiled GEMM body: Y[o][l] = (sum_c W[o][c] * X[c][l] + bias[o]) * scale
// O tile = 64 (blockIdx.y), L tile = 64 (blockIdx.x), K tile = 16.
// 256 threads, each computes a 4x4 micro-tile.
// ---------------------------------------------------------------------------
__device__ __forceinline__ void gemm64(const float* __restrict__ W,
                                       const float* __restrict__ bias,
                                       const float* __restrict__ X,
                                       float* __restrict__ Y,
                                       float scale)
{
    __shared__ float As[16][64];  // [k][o] (transposed W tile)
    __shared__ float Bs[16][64];  // [k][l]

    const int tid = threadIdx.x;
    const int tx = tid & 15;      // 0..15 -> l micro
    const int ty = tid >> 4;      // 0..15 -> o micro
    const int o0 = blockIdx.y * 64;
    const int l0 = blockIdx.x * 64;

    // A-tile loader mapping: 64 rows x 16 cols, float4 along k
    const int ar = tid >> 2;          // 0..63 (o within tile)
    const int ac = (tid & 3) * 4;     // 0,4,8,12 (k within tile)
    // B-tile loader mapping: 16 rows x 64 cols, float4 along l
    const int br = tid >> 4;          // 0..15 (k within tile)
    const int bc = (tid & 15) * 4;    // 0..60 (l within tile)

    float acc[4][4] = {};

    for (int k0 = 0; k0 < C_DIM; k0 += 16) {
        float4 a = *(const float4*)&W[(o0 + ar) * C_DIM + k0 + ac];
        float4 b = *(const float4*)&X[(k0 + br) * L_DIM + l0 + bc];
        As[ac + 0][ar] = a.x;
        As[ac + 1][ar] = a.y;
        As[ac + 2][ar] = a.z;
        As[ac + 3][ar] = a.w;
        *(float4*)&Bs[br][bc] = b;
        __syncthreads();

        #pragma unroll
        for (int k = 0; k < 16; k++) {
            float4 av = *(const float4*)&As[k][ty * 4];
            float4 bv = *(const float4*)&Bs[k][tx * 4];
            float aa[4] = {av.x, av.y, av.z, av.w};
            float bb[4] = {bv.x, bv.y, bv.z, bv.w};
            #pragma unroll
            for (int i = 0; i < 4; i++)
                #pragma unroll
                for (int j = 0; j < 4; j++)
                    acc[i][j] += aa[i] * bb[j];
        }
        __syncthreads();
    }

    #pragma unroll
    for (int i = 0; i < 4; i++) {
        int o = o0 + ty * 4 + i;
        float bi = bias[o];
        float4 r;
        r.x = (acc[i][0] + bi) * scale;
        r.y = (acc[i][1] + bi) * scale;
        r.z = (acc[i][2] + bi) * scale;
        r.w = (acc[i][3] + bi) * scale;
        *(float4*)&Y[o * L_DIM + l0 + tx * 4] = r;
    }
}

// Fused Q/K/V projection: grid.z = sel*16 + batch, sel in {0,1,2}
__global__ void __launch_bounds__(256)
proj_qkv_kernel(const float* __restrict__ wq, const float* __restrict__ bq,
                const float* __restrict__ wk, const float* __restrict__ bk,
                const float* __restrict__ wv, const float* __restrict__ bv,
                const float* __restrict__ x)
{
    const int z = blockIdx.z;
    const int b = z & 15;
    const int sel = z >> 4;
    const float* W;
    const float* bi;
    float* Y;
    float sc;
    if (sel == 0)      { W = wq; bi = bq; Y = g_q; sc = SCALE; }
    else if (sel == 1) { W = wk; bi = bk; Y = g_k; sc = 1.0f;  }
    else               { W = wv; bi = bv; Y = g_v; sc = 1.0f;  }
    gemm64(W, bi, x + (size_t)b * C_DIM * L_DIM, Y + (size_t)b * C_DIM * L_DIM, sc);
}

// Output projection: reads g_att, writes final output
__global__ void __launch_bounds__(256)
proj_o_kernel(const float* __restrict__ wo, const float* __restrict__ bo,
              float* __restrict__ out)
{
    const int b = blockIdx.z;
    gemm64(wo, bo, g_att + (size_t)b * C_DIM * L_DIM,
           out + (size_t)b * C_DIM * L_DIM, 1.0f);
}

// ---------------------------------------------------------------------------
// Flash attention: one thread owns one query position l.
// blockIdx.y = (b*8 + head), blockIdx.x = query block of 256.
// K/V tiles of 128 m-positions in smem as float4 along m:
// every LDS.128 feeds 4 FFMAs (broadcast across the warp).
// ---------------------------------------------------------------------------
__global__ void __launch_bounds__(256)
attn_kernel()
{
    const int bn = blockIdx.y;                       // 0..127
    const int l = blockIdx.x * 256 + threadIdx.x;    // query index
    const float* __restrict__ qp = g_q + (size_t)bn * DH * L_DIM;
    const float* __restrict__ kp = g_k + (size_t)bn * DH * L_DIM;
    const float* __restrict__ vp = g_v + (size_t)bn * DH * L_DIM;

    __shared__ float4 ks[DH][32];  // [d][m/4] for a 128-wide m tile
    __shared__ float4 vs[DH][32];

    float q[DH];
    #pragma unroll
    for (int d = 0; d < DH; d++) q[d] = qp[d * L_DIM + l];

    float acc[DH] = {};
    float mmax = -1e30f;
    float lsum = 0.0f;

    for (int m0 = 0; m0 < L_DIM; m0 += 128) {
        __syncthreads();
        #pragma unroll
        for (int i = 0; i < 4; i++) {
            int idx = threadIdx.x + i * 256;   // 0..1023
            int d = idx >> 5;                  // 0..31
            int g = idx & 31;                  // 0..31
            ks[d][g] = *(const float4*)&kp[d * L_DIM + m0 + g * 4];
            vs[d][g] = *(const float4*)&vp[d * L_DIM + m0 + g * 4];
        }
        __syncthreads();

        for (int c = 0; c < 32; c += 4) {      // 16 m-positions per chunk
            float s[16] = {};
            #pragma unroll
            for (int d = 0; d < DH; d++) {
                float qd = q[d];
                float4 kv[4] = {ks[d][c], ks[d][c + 1], ks[d][c + 2], ks[d][c + 3]};
                const float* kf = (const float*)kv;
                #pragma unroll
                for (int j = 0; j < 16; j++) s[j] += qd * kf[j];
            }
            float cm = s[0];
            #pragma unroll
            for (int j = 1; j < 16; j++) cm = fmaxf(cm, s[j]);
            float nm = fmaxf(mmax, cm);
            float corr = __expf(mmax - nm);
            float psum = 0.0f;
            #pragma unroll
            for (int j = 0; j < 16; j++) {
                s[j] = __expf(s[j] - nm);
                psum += s[j];
            }
            lsum = lsum * corr + psum;
            mmax = nm;
            #pragma unroll
            for (int d = 0; d < DH; d++) {
                float a = acc[d] * corr;
                float4 vv[4] = {vs[d][c], vs[d][c + 1], vs[d][c + 2], vs[d][c + 3]};
                const float* vf = (const float*)vv;
                #pragma unroll
                for (int j = 0; j < 16; j++) a += s[j] * vf[j];
                acc[d] = a;
            }
        }
    }

    float inv = 1.0f / lsum;
    float* __restrict__ op = g_att + (size_t)bn * DH * L_DIM;
    #pragma unroll
    for (int d = 0; d < DH; d++) op[d * L_DIM + l] = acc[d] * inv;
}

// ---------------------------------------------------------------------------
extern "C" void kernel_launch(void* const* d_in, const int* in_sizes, int n_in,
                              void* d_out, int out_size)
{
    const float* x  = (const float*)d_in[0];
    const float* wq = (const float*)d_in[1];
    const float* bq = (const float*)d_in[2];
    const float* wk = (const float*)d_in[3];
    const float* bk = (const float*)d_in[4];
    const float* wv = (const float*)d_in[5];
    const float* bv = (const float*)d_in[6];
    const float* wo = (const float*)d_in[7];
    const float* bo = (const float*)d_in[8];
    float* out = (float*)d_out;

    dim3 blk(256);
    proj_qkv_kernel<<<dim3(16, 4, 48), blk>>>(wq, bq, wk, bk, wv, bv, x);
    attn_kernel<<<dim3(4, 128), blk>>>();
    proj_o_kernel<<<dim3(16, 4, 16), blk>>>(wo, bo, out);
}